// round 16
// baseline (speedup 1.0000x reference)
#include <cuda_runtime.h>
#include <cuda_fp16.h>
#include <math.h>
#include <stdint.h>

// Problem constants: B=2,S=2048,H=2048,E=8,F=2048,top_k=2 (fp32 in/out)
#define T_TOK 4096
#define H_DIM 2048
#define E_NUM 8
#define F_DIM 2048

#define BM 128
#define MAX_TILES 72
#define MAX_SLOTS (T_TOK * 2 + E_NUM * BM)  // 9216
#define NST 32                               // K/64 stages
#define GEMM_GRID 296                        // 2 CTAs per SM
#define GTHREADS 512                         // 16 warps per CTA -> 32 warps/SM

#define NCHUNK 1024                          // w2 conversion chunks
#define CHUNK_F4 8192                        // float4 per chunk

// ---------------- static device scratch (pure fp16 operands) ----------------
__device__ __half g_xh[(size_t)T_TOK * H_DIM];
__device__ __half g_w1h[(size_t)E_NUM * H_DIM * F_DIM];  // [E][H][F]
__device__ __half g_w3h[(size_t)E_NUM * H_DIM * F_DIM];
__device__ __half g_w2h[(size_t)E_NUM * F_DIM * H_DIM];  // [E][F][H]
__device__ __half g_act[(size_t)MAX_SLOTS * F_DIM];

__device__ int   g_perm[MAX_SLOTS];
__device__ float g_slotw[MAX_SLOTS];
__device__ int   g_topi[T_TOK * 2];
__device__ float g_topw[T_TOK * 2];
__device__ int   g_tile_expert[MAX_TILES];
__device__ int   g_ntiles;

// dynamic scheduling state (reset every replay in assign_kernel)
__device__ int   g_jobctr;
__device__ int   g_convdone;                 // w2 chunks done
__device__ int   g_tile_done[MAX_TILES];

// ---------------- PTX helpers (plain compute_103-legal) ---------------------
__device__ __forceinline__ uint32_t smem_u32(const void* p) {
    uint32_t a;
    asm("{ .reg .u64 t; cvta.to.shared.u64 t, %1; cvt.u32.u64 %0, t; }" : "=r"(a) : "l"(p));
    return a;
}
__device__ __forceinline__ void cpa(uint32_t dst, const void* src) {
    asm volatile("cp.async.cg.shared.global [%0], [%1], 16;" :: "r"(dst), "l"(src));
}
#define CP_COMMIT() asm volatile("cp.async.commit_group;" ::: "memory")
#define CP_WAIT1()  asm volatile("cp.async.wait_group 1;" ::: "memory")

__device__ __forceinline__ void ldsm4(uint32_t* r, uint32_t addr) {
    asm volatile("ldmatrix.sync.aligned.m8n8.x4.shared.b16 {%0,%1,%2,%3}, [%4];"
                 : "=r"(r[0]), "=r"(r[1]), "=r"(r[2]), "=r"(r[3]) : "r"(addr));
}
__device__ __forceinline__ void ldsm4t(uint32_t* r, uint32_t addr) {
    asm volatile("ldmatrix.sync.aligned.m8n8.x4.trans.shared.b16 {%0,%1,%2,%3}, [%4];"
                 : "=r"(r[0]), "=r"(r[1]), "=r"(r[2]), "=r"(r[3]) : "r"(addr));
}
__device__ __forceinline__ void mma16816(float* d, const uint32_t* a, const uint32_t* b) {
    asm volatile(
        "mma.sync.aligned.m16n8k16.row.col.f32.f16.f16.f32 "
        "{%0,%1,%2,%3}, {%4,%5,%6,%7}, {%8,%9}, {%0,%1,%2,%3};"
        : "+f"(d[0]), "+f"(d[1]), "+f"(d[2]), "+f"(d[3])
        : "r"(a[0]), "r"(a[1]), "r"(a[2]), "r"(a[3]), "r"(b[0]), "r"(b[1]));
}

// ---------------- prep: zero(out) + router + convert x,w1,w3 ----------------
// 8 float4 per thread (MLP 8)
#define ZB8 1024                  // zero: T*H/4/2048
#define RB 512                    // router: T/8
#define XC8 1024                  // x convert
#define WC8 4096                  // per weight matrix
#define PREP_GRID (ZB8 + RB + XC8 + 2 * WC8)   // 10752

__global__ void prep_kernel(const float* __restrict__ x,
                            const float* __restrict__ gw,
                            const float* __restrict__ w1,
                            const float* __restrict__ w3,
                            float4* __restrict__ out) {
    long b = blockIdx.x;
    int tid = threadIdx.x;
    if (b < ZB8) {
        size_t base = (size_t)b * 2048 + tid;
#pragma unroll
        for (int it = 0; it < 8; it++)
            out[base + it * 256] = make_float4(0.f, 0.f, 0.f, 0.f);
        return;
    }
    b -= ZB8;
    if (b < RB) {
        int warp = tid >> 5, lane = tid & 31;
        int t = (int)b * 8 + warp;
        const float* xr = x + (size_t)t * H_DIM;
        float acc[E_NUM];
#pragma unroll
        for (int e = 0; e < E_NUM; e++) acc[e] = 0.f;
        for (int i = lane; i < H_DIM; i += 32) {
            float xv = xr[i];
#pragma unroll
            for (int e = 0; e < E_NUM; e++) acc[e] += xv * gw[e * H_DIM + i];
        }
#pragma unroll
        for (int e = 0; e < E_NUM; e++)
            for (int o = 16; o > 0; o >>= 1)
                acc[e] += __shfl_down_sync(0xffffffffu, acc[e], o);
        if (lane == 0) {
            float m = acc[0];
#pragma unroll
            for (int e = 1; e < E_NUM; e++) m = fmaxf(m, acc[e]);
            float p[E_NUM];
#pragma unroll
            for (int e = 0; e < E_NUM; e++) p[e] = expf(acc[e] - m);
            int a = 0;
#pragma unroll
            for (int e = 1; e < E_NUM; e++) if (p[e] > p[a]) a = e;
            int bb = (a == 0) ? 1 : 0;
#pragma unroll
            for (int e = 0; e < E_NUM; e++)
                if (e != a && p[e] > p[bb]) bb = e;
            float denom = p[a] + p[bb];
            g_topi[t * 2 + 0] = a;
            g_topi[t * 2 + 1] = bb;
            g_topw[t * 2 + 0] = p[a] / denom;
            g_topw[t * 2 + 1] = p[bb] / denom;
        }
        return;
    }
    b -= RB;
    const float* src;
    __half* dst;
    if (b < XC8) {
        src = x; dst = g_xh;
    } else {
        b -= XC8;
        int w = (int)(b >> 12);
        b &= (WC8 - 1);
        src = (w == 0) ? w1 : w3;
        dst = (w == 0) ? g_w1h : g_w3h;
    }
    size_t base = (size_t)b * 2048 + tid;
#pragma unroll
    for (int it = 0; it < 8; it++) {
        size_t i = base + it * 256;
        float4 v = ((const float4*)src)[i];
        __half2 p0 = __floats2half2_rn(v.x, v.y);
        __half2 p1 = __floats2half2_rn(v.z, v.w);
        ((uint2*)dst)[i] = make_uint2(*(uint32_t*)&p0, *(uint32_t*)&p1);
    }
}

// ---------------- assign (+ reset scheduling counters each replay) ----------
__global__ void assign_kernel() {
    __shared__ int cnt[E_NUM], cur[E_NUM], off[E_NUM], pcnt[E_NUM];
    int tid = threadIdx.x;
    if (tid < E_NUM) { cnt[tid] = 0; cur[tid] = 0; }
    if (tid == 0) { g_jobctr = 0; g_convdone = 0; }
    if (tid < MAX_TILES) g_tile_done[tid] = 0;
    __syncthreads();
    for (int i = tid; i < T_TOK * 2; i += blockDim.x)
        atomicAdd(&cnt[g_topi[i]], 1);
    __syncthreads();
    if (tid == 0) {
        int o = 0, mt = 0;
        for (int e = 0; e < E_NUM; e++) {
            off[e] = o;
            int pc = ((cnt[e] + BM - 1) / BM) * BM;
            pcnt[e] = pc;
            int tiles = pc / BM;
            for (int i = 0; i < tiles; i++) g_tile_expert[mt + i] = e;
            mt += tiles;
            o += pc;
        }
        g_ntiles = mt;
        for (int i = mt; i < MAX_TILES; i++) g_tile_expert[i] = 0;
    }
    __syncthreads();
    for (int i = tid; i < T_TOK * 2; i += blockDim.x) {
        int e = g_topi[i];
        int pos = off[e] + atomicAdd(&cur[e], 1);
        g_perm[pos] = i >> 1;
        g_slotw[pos] = g_topw[i];
    }
    __syncthreads();
    for (int j = tid; j < E_NUM * BM; j += blockDim.x) {
        int e = j / BM;
        int i = cnt[e] + (j % BM);
        if (i < pcnt[e]) {
            g_perm[off[e] + i] = 0;
            g_slotw[off[e] + i] = 0.f;
        }
    }
}

// ---------------- w2 conversion chunk (512-thread blocks) -------------------
__device__ __forceinline__ void conv_chunk(int c, const float* __restrict__ w2f) {
    if (c < NCHUNK) {
        size_t base = (size_t)c * CHUNK_F4 + threadIdx.x;
#pragma unroll 4
        for (int it = 0; it < CHUNK_F4 / 512; it++) {
            size_t i = base + (size_t)it * 512;
            float4 v = ((const float4*)w2f)[i];
            __half2 p0 = __floats2half2_rn(v.x, v.y);
            __half2 p1 = __floats2half2_rn(v.z, v.w);
            ((uint2*)g_w2h)[i] = make_uint2(*(uint32_t*)&p0, *(uint32_t*)&p1);
        }
        __threadfence();
    }
    __syncthreads();
    if (threadIdx.x == 0 && c < NCHUNK) atomicAdd(&g_convdone, 1);
}

// ============================================================================
// Fused persistent GEMM kernel: 512 threads, 2 CTAs/SM (32 warps/SM).
// 16 warps = 4m x 4n. gemm1 warp tile 32m x 16n per matrix; gemm2 32m x 32n.
// Jobs [0, NG1): gemm1; [NG1, NTOT): gemm2. w2 conv chunks interleaved.
// ============================================================================
#define G_STAGE1 36864
#define G_STAGE2 35840
#define G_SMEM (1024 + 3 * G_STAGE1)

__global__ __launch_bounds__(GTHREADS, 2) void moe_gemm_kernel(const float* __restrict__ w2f,
                                                               float* __restrict__ out) {
    extern __shared__ char smem[];
    int* rows = (int*)smem;
    float* ws = (float*)(smem + 512);
    const uint32_t sb = smem_u32(smem);
    const int tid = threadIdx.x;
    const int lane = tid & 31, wid = tid >> 5;
    const int warpm = wid & 3, warpn = wid >> 2;   // 4m x 4n

    const int a_lrow = (lane < 16) ? lane : (lane - 16);
    const int a_lkoff = (lane >= 16) ? 8 : 0;
    const int b_lk = ((lane >> 3) & 1) * 8 + (lane & 7);
    const int b_ln = (lane >> 4) * 8;

    const int NG1 = g_ntiles * 32;
    const int NTOT = g_ntiles * 48;
    int conv_next = 0;
    __shared__ int s_job;

    for (;;) {
        __syncthreads();  // retire previous job's buffers + rows/ws
        if (tid == 0) s_job = atomicAdd(&g_jobctr, 1);
        __syncthreads();
        const int job = s_job;
        if (job >= NTOT) break;

        if (job < NG1) {
            // ================= GEMM1 job =================
            const int mt = job >> 5;
            const int n0 = (job & 31) * 64;
            const int e = g_tile_expert[mt];
            const int m0 = mt * BM;
            const int m0w = warpm * 32, n0w = warpn * 16;

            if (tid < 128) rows[tid] = g_perm[m0 + tid];
            __syncthreads();

            // loaders: A row = tid>>2 (0..127), 32B; B: 256 thr/mat, row=k
            const int ar = tid >> 2;
            const uint32_t qa = (uint32_t)(tid & 3) * 32;
            const char* srcA = (const char*)(g_xh + (size_t)rows[ar] * H_DIM) + qa;
            const uint32_t dA = (uint32_t)ar * 144 + qa;
            const int matl = tid >> 8;                 // 0 or 1
            const int kr = (tid & 255) >> 2;           // 0..63
            const uint32_t qb = (uint32_t)(tid & 3) * 32;
            const char* srcB = (const char*)((matl ? g_w3h : g_w1h) +
                               (size_t)e * H_DIM * F_DIM + (size_t)kr * F_DIM + n0) + qb;
            const uint32_t dB = 18432u + (uint32_t)matl * 9216u + (uint32_t)kr * 144 + qb;

            float acc1[2][2][4], acc3[2][2][4];
#pragma unroll
            for (int mi = 0; mi < 2; mi++)
#pragma unroll
                for (int ni = 0; ni < 2; ni++)
#pragma unroll
                    for (int r = 0; r < 4; r++) { acc1[mi][ni][r] = 0.f; acc3[mi][ni][r] = 0.f; }

#define G1_ISSUE(p)                                                               \
    {                                                                             \
        uint32_t st = sb + 1024 + (uint32_t)((p) % 3) * G_STAGE1;                 \
        cpa(st + dA, srcA + (size_t)(p) * 128);                                   \
        cpa(st + dA + 16, srcA + (size_t)(p) * 128 + 16);                         \
        const char* bs = srcB + (size_t)(p) * 64 * F_DIM * 2;                     \
        cpa(st + dB, bs);                                                         \
        cpa(st + dB + 16, bs + 16);                                               \
    }

            G1_ISSUE(0); CP_COMMIT();
            G1_ISSUE(1); CP_COMMIT();

            for (int s = 0; s < NST; s++) {
                CP_WAIT1();
                __syncthreads();
                if (s + 2 < NST) { G1_ISSUE(s + 2); }
                CP_COMMIT();

                const uint32_t st = sb + 1024 + (uint32_t)(s % 3) * G_STAGE1;
#pragma unroll
                for (int k16 = 0; k16 < 4; k16++) {
                    const int kl = k16 * 16;
                    uint32_t a[2][4];
#pragma unroll
                    for (int mi = 0; mi < 2; mi++)
                        ldsm4(a[mi], st + (uint32_t)((m0w + mi * 16 + a_lrow) * 144 + (kl + a_lkoff) * 2));
#pragma unroll
                    for (int mat = 0; mat < 2; mat++) {
                        uint32_t t4[4];
                        ldsm4t(t4, st + 18432u + (uint32_t)mat * 9216u +
                                   (uint32_t)((kl + b_lk) * 144 + (n0w + b_ln) * 2));
#pragma unroll
                        for (int mi = 0; mi < 2; mi++) {
                            float* ac0 = mat ? acc3[mi][0] : acc1[mi][0];
                            mma16816(ac0, a[mi], t4);
                            float* ac1 = mat ? acc3[mi][1] : acc1[mi][1];
                            mma16816(ac1, a[mi], t4 + 2);
                        }
                    }
                }
            }

            // epilogue: SwiGLU -> fp16 act (warp: 32m x 16n)
            const int g = lane >> 2, tq = lane & 3;
#pragma unroll
            for (int mi = 0; mi < 2; mi++)
#pragma unroll
                for (int rp = 0; rp < 2; rp++) {
                    const int slot = m0 + m0w + mi * 16 + rp * 8 + g;
#pragma unroll
                    for (int ni = 0; ni < 2; ni++) {
                        float h1a = acc1[mi][ni][rp * 2 + 0], h1b = acc1[mi][ni][rp * 2 + 1];
                        float h3a = acc3[mi][ni][rp * 2 + 0], h3b = acc3[mi][ni][rp * 2 + 1];
                        float va = h1a * h3a / (1.f + __expf(-h1a));
                        float vb = h1b * h3b / (1.f + __expf(-h1b));
                        __half2 pk = __floats2half2_rn(va, vb);
                        size_t o = (size_t)slot * F_DIM + n0 + n0w + ni * 8 + tq * 2;
                        *(uint32_t*)((char*)g_act + o * 2) = *(uint32_t*)&pk;
                    }
                }
            // publish this gemm1 job (release)
            __threadfence();
            __syncthreads();
            if (tid == 0) atomicAdd(&g_tile_done[mt], 1);
            // interleaved w2 conversion (rides the idle DRAM)
            if (conv_next < 4) { conv_chunk(blockIdx.x + conv_next * GEMM_GRID, w2f); conv_next++; }
        } else {
            // flush this CTA's pending conversion chunks BEFORE any wait
            while (conv_next < 4) { conv_chunk(blockIdx.x + conv_next * GEMM_GRID, w2f); conv_next++; }

            // ================= GEMM2 job =================
            const int j2 = job - NG1;
            const int mt = j2 >> 4;
            const int n0 = (j2 & 15) * 128;
            const int e = g_tile_expert[mt];
            const int m0 = mt * BM;
            const int m0w = warpm * 32, n0w = warpn * 32;

            if (tid == 0) {
                while (atomicAdd(&g_convdone, 0) < NCHUNK) __nanosleep(200);
                while (atomicAdd(&g_tile_done[mt], 0) < 32) __nanosleep(200);
                __threadfence();  // acquire
            }
            __syncthreads();

            if (tid < 128) {
                rows[tid] = g_perm[m0 + tid];
                ws[tid] = g_slotw[m0 + tid];
            }
            __syncthreads();

            const int ar = tid >> 2;
            const uint32_t qa = (uint32_t)(tid & 3) * 32;
            const char* srcA = (const char*)(g_act + (size_t)(m0 + ar) * F_DIM) + qa;
            const uint32_t dA = (uint32_t)ar * 144 + qa;
            const int kr = tid >> 3;                   // 0..63
            const uint32_t qb = (uint32_t)(tid & 7) * 32;
            const char* srcB = (const char*)(g_w2h + (size_t)e * F_DIM * H_DIM +
                               (size_t)kr * H_DIM + n0) + qb;
            const uint32_t dB = 18432u + (uint32_t)kr * 272 + qb;

            float acc[2][4][4];
#pragma unroll
            for (int mi = 0; mi < 2; mi++)
#pragma unroll
                for (int ni = 0; ni < 4; ni++)
#pragma unroll
                    for (int r = 0; r < 4; r++) acc[mi][ni][r] = 0.f;

#define G2_ISSUE(p)                                                               \
    {                                                                             \
        uint32_t st = sb + 1024 + (uint32_t)((p) % 3) * G_STAGE2;                 \
        cpa(st + dA, srcA + (size_t)(p) * 128);                                   \
        cpa(st + dA + 16, srcA + (size_t)(p) * 128 + 16);                         \
        const char* bs = srcB + (size_t)(p) * 64 * H_DIM * 2;                     \
        cpa(st + dB, bs);                                                         \
        cpa(st + dB + 16, bs + 16);                                               \
    }

            G2_ISSUE(0); CP_COMMIT();
            G2_ISSUE(1); CP_COMMIT();

            for (int s = 0; s < NST; s++) {
                CP_WAIT1();
                __syncthreads();
                if (s + 2 < NST) { G2_ISSUE(s + 2); }
                CP_COMMIT();

                const uint32_t st = sb + 1024 + (uint32_t)(s % 3) * G_STAGE2;
#pragma unroll
                for (int k16 = 0; k16 < 4; k16++) {
                    const int kl = k16 * 16;
                    uint32_t a[2][4];
#pragma unroll
                    for (int mi = 0; mi < 2; mi++)
                        ldsm4(a[mi], st + (uint32_t)((m0w + mi * 16 + a_lrow) * 144 + (kl + a_lkoff) * 2));
#pragma unroll
                    for (int nh = 0; nh < 2; nh++) {
                        uint32_t t4[4];
                        ldsm4t(t4, st + 18432u +
                                   (uint32_t)((kl + b_lk) * 272 + (n0w + nh * 16 + b_ln) * 2));
#pragma unroll
                        for (int mi = 0; mi < 2; mi++) {
                            mma16816(acc[mi][nh * 2 + 0], a[mi], t4);
                            mma16816(acc[mi][nh * 2 + 1], a[mi], t4 + 2);
                        }
                    }
                }
            }

            // epilogue: weighted scatter-add (warp: 32m x 32n)
            const int g = lane >> 2, tq = lane & 3;
#pragma unroll
            for (int mi = 0; mi < 2; mi++)
#pragma unroll
                for (int rp = 0; rp < 2; rp++) {
                    const int rloc = m0w + mi * 16 + rp * 8 + g;
                    const int tok = rows[rloc];
                    const float wt = ws[rloc];
                    if (wt != 0.f) {
                        float* dst = out + (size_t)tok * H_DIM + n0 + n0w + tq * 2;
#pragma unroll
                        for (int ni = 0; ni < 4; ni++) {
                            atomicAdd(dst + ni * 8 + 0, wt * acc[mi][ni][rp * 2 + 0]);
                            atomicAdd(dst + ni * 8 + 1, wt * acc[mi][ni][rp * 2 + 1]);
                        }
                    }
                }
        }
    }

    // safety: finish any conversion chunks this CTA still owns
    while (conv_next < 4) { conv_chunk(blockIdx.x + conv_next * GEMM_GRID, w2f); conv_next++; }
}

// ---------------- launch ----------------------------------------------------
extern "C" void kernel_launch(void* const* d_in, const int* in_sizes, int n_in,
                              void* d_out, int out_size) {
    const float* x  = (const float*)d_in[0];
    const float* gw = (const float*)d_in[1];
    const float* w1 = (const float*)d_in[2];
    const float* w2 = (const float*)d_in[3];
    const float* w3 = (const float*)d_in[4];
    float* out = (float*)d_out;

    cudaFuncSetAttribute(moe_gemm_kernel, cudaFuncAttributeMaxDynamicSharedMemorySize, G_SMEM);

    prep_kernel<<<PREP_GRID, 256>>>(x, gw, w1, w3, (float4*)out);
    assign_kernel<<<1, 256>>>();
    moe_gemm_kernel<<<GEMM_GRID, GTHREADS, G_SMEM>>>(w2, out);
}

// round 17
// speedup vs baseline: 1.1531x; 1.1531x over previous
#include <cuda_runtime.h>
#include <cuda_fp16.h>
#include <math.h>
#include <stdint.h>

// Problem constants: B=2,S=2048,H=2048,E=8,F=2048,top_k=2 (fp32 in/out)
#define T_TOK 4096
#define H_DIM 2048
#define E_NUM 8
#define F_DIM 2048

#define BM 128
#define MAX_TILES 72
#define MAX_SLOTS (T_TOK * 2 + E_NUM * BM)  // 9216
#define NST 32                               // K/64 stages
#define GEMM_GRID 296                        // 2 CTAs per SM

#define NCHUNK 1024                          // w2 conversion chunks
#define CHUNK_F4 8192                        // float4 per chunk

// ---------------- static device scratch (pure fp16 operands) ----------------
__device__ __half g_xh[(size_t)T_TOK * H_DIM];
__device__ __half g_w1h[(size_t)E_NUM * H_DIM * F_DIM];  // [E][H][F]
__device__ __half g_w3h[(size_t)E_NUM * H_DIM * F_DIM];
__device__ __half g_w2h[(size_t)E_NUM * F_DIM * H_DIM];  // [E][F][H]
__device__ __half g_act[(size_t)MAX_SLOTS * F_DIM];

__device__ int   g_perm[MAX_SLOTS];
__device__ float g_slotw[MAX_SLOTS];
__device__ int   g_topi[T_TOK * 2];
__device__ float g_topw[T_TOK * 2];
__device__ int   g_tile_expert[MAX_TILES];
__device__ int   g_ntiles;

// dynamic scheduling state (reset every replay in assign_kernel)
__device__ int   g_jobctr;
__device__ int   g_convdone;                 // w2 chunks done
__device__ int   g_tile_done[MAX_TILES];

// ---------------- PTX helpers (plain compute_103-legal) ---------------------
__device__ __forceinline__ uint32_t smem_u32(const void* p) {
    uint32_t a;
    asm("{ .reg .u64 t; cvta.to.shared.u64 t, %1; cvt.u32.u64 %0, t; }" : "=r"(a) : "l"(p));
    return a;
}
__device__ __forceinline__ void cpa(uint32_t dst, const void* src) {
    asm volatile("cp.async.cg.shared.global [%0], [%1], 16;" :: "r"(dst), "l"(src));
}
#define CP_COMMIT() asm volatile("cp.async.commit_group;" ::: "memory")
#define CP_WAIT1()  asm volatile("cp.async.wait_group 1;" ::: "memory")

__device__ __forceinline__ void ldsm4(uint32_t* r, uint32_t addr) {
    asm volatile("ldmatrix.sync.aligned.m8n8.x4.shared.b16 {%0,%1,%2,%3}, [%4];"
                 : "=r"(r[0]), "=r"(r[1]), "=r"(r[2]), "=r"(r[3]) : "r"(addr));
}
__device__ __forceinline__ void ldsm4t(uint32_t* r, uint32_t addr) {
    asm volatile("ldmatrix.sync.aligned.m8n8.x4.trans.shared.b16 {%0,%1,%2,%3}, [%4];"
                 : "=r"(r[0]), "=r"(r[1]), "=r"(r[2]), "=r"(r[3]) : "r"(addr));
}
__device__ __forceinline__ void mma16816(float* d, const uint32_t* a, const uint32_t* b) {
    asm volatile(
        "mma.sync.aligned.m16n8k16.row.col.f32.f16.f16.f32 "
        "{%0,%1,%2,%3}, {%4,%5,%6,%7}, {%8,%9}, {%0,%1,%2,%3};"
        : "+f"(d[0]), "+f"(d[1]), "+f"(d[2]), "+f"(d[3])
        : "r"(a[0]), "r"(a[1]), "r"(a[2]), "r"(a[3]), "r"(b[0]), "r"(b[1]));
}

// ---------------- prep: zero(out) + router + convert x,w1,w3 ----------------
// 4 float4 per thread (MLP 4) -> DRAM-roofline conversion
#define ZB4 2048                  // zero: T*H/4/1024
#define RB 512                    // router: T/8
#define XC4 2048                  // x convert: T*H/4/1024
#define WC4 8192                  // per weight matrix: E*H*F/4/1024
#define PREP_GRID (ZB4 + RB + XC4 + 2 * WC4)   // 20992

__global__ void prep_kernel(const float* __restrict__ x,
                            const float* __restrict__ gw,
                            const float* __restrict__ w1,
                            const float* __restrict__ w3,
                            float4* __restrict__ out) {
    long b = blockIdx.x;
    int tid = threadIdx.x;
    if (b < ZB4) {
        size_t base = (size_t)b * 1024 + tid;
#pragma unroll
        for (int it = 0; it < 4; it++)
            out[base + it * 256] = make_float4(0.f, 0.f, 0.f, 0.f);
        return;
    }
    b -= ZB4;
    if (b < RB) {
        int warp = tid >> 5, lane = tid & 31;
        int t = (int)b * 8 + warp;
        const float* xr = x + (size_t)t * H_DIM;
        float acc[E_NUM];
#pragma unroll
        for (int e = 0; e < E_NUM; e++) acc[e] = 0.f;
        for (int i = lane; i < H_DIM; i += 32) {
            float xv = xr[i];
#pragma unroll
            for (int e = 0; e < E_NUM; e++) acc[e] += xv * gw[e * H_DIM + i];
        }
#pragma unroll
        for (int e = 0; e < E_NUM; e++)
            for (int o = 16; o > 0; o >>= 1)
                acc[e] += __shfl_down_sync(0xffffffffu, acc[e], o);
        if (lane == 0) {
            float m = acc[0];
#pragma unroll
            for (int e = 1; e < E_NUM; e++) m = fmaxf(m, acc[e]);
            float p[E_NUM];
#pragma unroll
            for (int e = 0; e < E_NUM; e++) p[e] = expf(acc[e] - m);
            int a = 0;
#pragma unroll
            for (int e = 1; e < E_NUM; e++) if (p[e] > p[a]) a = e;
            int bb = (a == 0) ? 1 : 0;
#pragma unroll
            for (int e = 0; e < E_NUM; e++)
                if (e != a && p[e] > p[bb]) bb = e;
            float denom = p[a] + p[bb];
            g_topi[t * 2 + 0] = a;
            g_topi[t * 2 + 1] = bb;
            g_topw[t * 2 + 0] = p[a] / denom;
            g_topw[t * 2 + 1] = p[bb] / denom;
        }
        return;
    }
    b -= RB;
    const float* src;
    __half* dst;
    if (b < XC4) {
        src = x; dst = g_xh;
    } else {
        b -= XC4;
        int w = (int)(b >> 13);
        b &= (WC4 - 1);
        src = (w == 0) ? w1 : w3;
        dst = (w == 0) ? g_w1h : g_w3h;
    }
    size_t base = (size_t)b * 1024 + tid;
#pragma unroll
    for (int it = 0; it < 4; it++) {
        size_t i = base + it * 256;
        float4 v = ((const float4*)src)[i];
        __half2 p0 = __floats2half2_rn(v.x, v.y);
        __half2 p1 = __floats2half2_rn(v.z, v.w);
        ((uint2*)dst)[i] = make_uint2(*(uint32_t*)&p0, *(uint32_t*)&p1);
    }
}

// ---------------- assign (+ reset scheduling counters each replay) ----------
__global__ void assign_kernel() {
    __shared__ int cnt[E_NUM], cur[E_NUM], off[E_NUM], pcnt[E_NUM];
    int tid = threadIdx.x;
    if (tid < E_NUM) { cnt[tid] = 0; cur[tid] = 0; }
    if (tid == 0) { g_jobctr = 0; g_convdone = 0; }
    if (tid < MAX_TILES) g_tile_done[tid] = 0;
    __syncthreads();
    for (int i = tid; i < T_TOK * 2; i += blockDim.x)
        atomicAdd(&cnt[g_topi[i]], 1);
    __syncthreads();
    if (tid == 0) {
        int o = 0, mt = 0;
        for (int e = 0; e < E_NUM; e++) {
            off[e] = o;
            int pc = ((cnt[e] + BM - 1) / BM) * BM;
            pcnt[e] = pc;
            int tiles = pc / BM;
            for (int i = 0; i < tiles; i++) g_tile_expert[mt + i] = e;
            mt += tiles;
            o += pc;
        }
        g_ntiles = mt;
        for (int i = mt; i < MAX_TILES; i++) g_tile_expert[i] = 0;
    }
    __syncthreads();
    for (int i = tid; i < T_TOK * 2; i += blockDim.x) {
        int e = g_topi[i];
        int pos = off[e] + atomicAdd(&cur[e], 1);
        g_perm[pos] = i >> 1;
        g_slotw[pos] = g_topw[i];
    }
    __syncthreads();
    for (int j = tid; j < E_NUM * BM; j += blockDim.x) {
        int e = j / BM;
        int i = cnt[e] + (j % BM);
        if (i < pcnt[e]) {
            g_perm[off[e] + i] = 0;
            g_slotw[off[e] + i] = 0.f;
        }
    }
}

// ---------------- w2 conversion chunk (runs inside fused GEMM kernel) -------
__device__ __forceinline__ void conv_chunk(int c, const float* __restrict__ w2f) {
    if (c < NCHUNK) {
        size_t base = (size_t)c * CHUNK_F4 + threadIdx.x;
#pragma unroll 4
        for (int it = 0; it < CHUNK_F4 / 256; it++) {
            size_t i = base + (size_t)it * 256;
            float4 v = ((const float4*)w2f)[i];
            __half2 p0 = __floats2half2_rn(v.x, v.y);
            __half2 p1 = __floats2half2_rn(v.z, v.w);
            ((uint2*)g_w2h)[i] = make_uint2(*(uint32_t*)&p0, *(uint32_t*)&p1);
        }
        __threadfence();
    }
    __syncthreads();
    if (threadIdx.x == 0 && c < NCHUNK) atomicAdd(&g_convdone, 1);
}

// ============================================================================
// Fused persistent GEMM kernel (2 CTAs/SM): dynamic job counter.
// Jobs [0, NG1): gemm1 tiles (mt = j>>5, n0 = (j&31)*64)  -> act
// Jobs [NG1, NG1+NG2): gemm2 tiles (mt = j>>4, n0 = (j&15)*128) -> out
// w2 fp32->fp16 conversion chunks interleaved after early gemm1 jobs.
// ============================================================================
#define G_STAGE1 36864
#define G_STAGE2 35840
#define G_SMEM (1024 + 3 * G_STAGE1)

__global__ __launch_bounds__(256, 2) void moe_gemm_kernel(const float* __restrict__ w2f,
                                                          float* __restrict__ out) {
    extern __shared__ char smem[];
    int* rows = (int*)smem;
    float* ws = (float*)(smem + 512);
    const uint32_t sb = smem_u32(smem);
    const int tid = threadIdx.x;
    const int lane = tid & 31, wid = tid >> 5;
    const int warpm = wid & 3, warpn = wid >> 2;

    const int a_lrow = (lane < 16) ? lane : (lane - 16);
    const int a_lkoff = (lane >= 16) ? 8 : 0;
    const int b_lk = ((lane >> 3) & 1) * 8 + (lane & 7);
    const int b_ln = (lane >> 4) * 8;

    const int NG1 = g_ntiles * 32;
    const int NTOT = g_ntiles * 48;
    int conv_next = 0;
    __shared__ int s_job;

    for (;;) {
        __syncthreads();  // retire previous job's buffers + rows/ws
        if (tid == 0) s_job = atomicAdd(&g_jobctr, 1);
        __syncthreads();
        const int job = s_job;
        if (job >= NTOT) break;

        if (job < NG1) {
            // ================= GEMM1 job =================
            const int mt = job >> 5;
            const int n0 = (job & 31) * 64;
            const int e = g_tile_expert[mt];
            const int m0 = mt * BM;
            const int m0w = warpm * 32, n0w = warpn * 32;
            const uint32_t q = (uint32_t)(tid & 7) * 16;
            const int krow_b = tid >> 3;

            if (tid < 128) rows[tid] = g_perm[m0 + tid];
            __syncthreads();

            const char* srcA[4];
            uint32_t dA[4];
#pragma unroll
            for (int t = 0; t < 4; t++) {
                int r = (tid >> 3) + t * 32;
                srcA[t] = (const char*)(g_xh + (size_t)rows[r] * H_DIM) + q;
                dA[t] = (uint32_t)r * 144 + q;
            }
            const char* wbase[2] = {(const char*)(g_w1h + (size_t)e * H_DIM * F_DIM),
                                    (const char*)(g_w3h + (size_t)e * H_DIM * F_DIM)};

            float acc1[2][4][4], acc3[2][4][4];
#pragma unroll
            for (int mi = 0; mi < 2; mi++)
#pragma unroll
                for (int ni = 0; ni < 4; ni++)
#pragma unroll
                    for (int r = 0; r < 4; r++) { acc1[mi][ni][r] = 0.f; acc3[mi][ni][r] = 0.f; }

#define G1_ISSUE(p)                                                               \
    {                                                                             \
        uint32_t st = sb + 1024 + (uint32_t)((p) % 3) * G_STAGE1;                 \
        size_t kb = (size_t)(p) * 64 * 2;                                         \
        cpa(st + dA[0], srcA[0] + kb);                                            \
        cpa(st + dA[1], srcA[1] + kb);                                            \
        cpa(st + dA[2], srcA[2] + kb);                                            \
        cpa(st + dA[3], srcA[3] + kb);                                            \
        _Pragma("unroll")                                                         \
        for (int t = 0; t < 4; t++) {                                             \
            int mat = t >> 1;                                                     \
            int kr = krow_b + (t & 1) * 32;                                       \
            const char* bs = wbase[mat] +                                         \
                (((size_t)(p) * 64 + kr) * F_DIM + n0) * 2 + q;                   \
            cpa(st + 18432u + (uint32_t)mat * 9216u + (uint32_t)kr * 144 + q, bs);\
        }                                                                         \
    }

            G1_ISSUE(0); CP_COMMIT();
            G1_ISSUE(1); CP_COMMIT();

            for (int s = 0; s < NST; s++) {
                CP_WAIT1();
                __syncthreads();
                if (s + 2 < NST) { G1_ISSUE(s + 2); }
                CP_COMMIT();

                const uint32_t st = sb + 1024 + (uint32_t)(s % 3) * G_STAGE1;
#pragma unroll
                for (int k16 = 0; k16 < 4; k16++) {
                    const int kl = k16 * 16;
                    uint32_t a[2][4];
#pragma unroll
                    for (int mi = 0; mi < 2; mi++)
                        ldsm4(a[mi], st + (uint32_t)((m0w + mi * 16 + a_lrow) * 144 + (kl + a_lkoff) * 2));
#pragma unroll
                    for (int mat = 0; mat < 2; mat++)
#pragma unroll
                        for (int nh = 0; nh < 2; nh++) {
                            uint32_t t4[4];
                            ldsm4t(t4, st + 18432u + (uint32_t)mat * 9216u +
                                       (uint32_t)((kl + b_lk) * 144 + (n0w + nh * 16 + b_ln) * 2));
#pragma unroll
                            for (int mi = 0; mi < 2; mi++) {
                                float* ac0 = mat ? acc3[mi][nh * 2] : acc1[mi][nh * 2];
                                mma16816(ac0, a[mi], t4);
                                float* ac1 = mat ? acc3[mi][nh * 2 + 1] : acc1[mi][nh * 2 + 1];
                                mma16816(ac1, a[mi], t4 + 2);
                            }
                        }
                }
            }

            // epilogue: SwiGLU -> fp16 act
            const int g = lane >> 2, tq = lane & 3;
#pragma unroll
            for (int mi = 0; mi < 2; mi++)
#pragma unroll
                for (int rp = 0; rp < 2; rp++) {
                    const int slot = m0 + m0w + mi * 16 + rp * 8 + g;
#pragma unroll
                    for (int ni = 0; ni < 4; ni++) {
                        float h1a = acc1[mi][ni][rp * 2 + 0], h1b = acc1[mi][ni][rp * 2 + 1];
                        float h3a = acc3[mi][ni][rp * 2 + 0], h3b = acc3[mi][ni][rp * 2 + 1];
                        float va = h1a * h3a / (1.f + __expf(-h1a));
                        float vb = h1b * h3b / (1.f + __expf(-h1b));
                        __half2 pk = __floats2half2_rn(va, vb);
                        size_t o = (size_t)slot * F_DIM + n0 + n0w + ni * 8 + tq * 2;
                        *(uint32_t*)((char*)g_act + o * 2) = *(uint32_t*)&pk;
                    }
                }
            // publish this gemm1 job (release)
            __threadfence();
            __syncthreads();
            if (tid == 0) atomicAdd(&g_tile_done[mt], 1);
            // interleaved w2 conversion (rides the idle DRAM)
            if (conv_next < 4) { conv_chunk(blockIdx.x + conv_next * GEMM_GRID, w2f); conv_next++; }
        } else {
            // flush this CTA's pending conversion chunks BEFORE any wait
            while (conv_next < 4) { conv_chunk(blockIdx.x + conv_next * GEMM_GRID, w2f); conv_next++; }

            // ================= GEMM2 job =================
            const int j2 = job - NG1;
            const int mt = j2 >> 4;
            const int n0 = (j2 & 15) * 128;
            const int e = g_tile_expert[mt];
            const int m0 = mt * BM;
            const int m0w = warpm * 32, n0w = warpn * 64;
            const uint32_t qa = (uint32_t)(tid & 7) * 16;
            const int ra = tid >> 3;
            const uint32_t qb = (uint32_t)(tid & 15) * 16;
            const int rb = tid >> 4;

            if (tid == 0) {
                while (atomicAdd(&g_convdone, 0) < NCHUNK) __nanosleep(200);
                while (atomicAdd(&g_tile_done[mt], 0) < 32) __nanosleep(200);
                __threadfence();  // acquire
            }
            __syncthreads();

            if (tid < 128) {
                rows[tid] = g_perm[m0 + tid];
                ws[tid] = g_slotw[m0 + tid];
            }
            __syncthreads();

            const char* srcA = (const char*)(g_act + (size_t)(m0 + ra) * F_DIM) + qa;
            const char* srcB = (const char*)(g_w2h + (size_t)e * F_DIM * H_DIM + n0) + qb;

            float acc[2][8][4];
#pragma unroll
            for (int mi = 0; mi < 2; mi++)
#pragma unroll
                for (int ni = 0; ni < 8; ni++)
#pragma unroll
                    for (int r = 0; r < 4; r++) acc[mi][ni][r] = 0.f;

#define G2_ISSUE(p)                                                               \
    {                                                                             \
        uint32_t st = sb + 1024 + (uint32_t)((p) % 3) * G_STAGE2;                 \
        size_t kb = (size_t)(p) * 64 * 2;                                         \
        _Pragma("unroll")                                                         \
        for (int t = 0; t < 4; t++) {                                             \
            int r = ra + t * 32;                                                  \
            cpa(st + (uint32_t)r * 144 + qa,                                      \
                srcA + (size_t)t * 32 * F_DIM * 2 + kb);                          \
        }                                                                         \
        _Pragma("unroll")                                                         \
        for (int t = 0; t < 4; t++) {                                             \
            int kr = rb + t * 16;                                                 \
            cpa(st + 18432u + (uint32_t)kr * 272 + qb,                            \
                srcB + ((size_t)(p) * 64 + kr) * H_DIM * 2);                      \
        }                                                                         \
    }

            G2_ISSUE(0); CP_COMMIT();
            G2_ISSUE(1); CP_COMMIT();

            for (int s = 0; s < NST; s++) {
                CP_WAIT1();
                __syncthreads();
                if (s + 2 < NST) { G2_ISSUE(s + 2); }
                CP_COMMIT();

                const uint32_t st = sb + 1024 + (uint32_t)(s % 3) * G_STAGE2;
#pragma unroll
                for (int k16 = 0; k16 < 4; k16++) {
                    const int kl = k16 * 16;
                    uint32_t a[2][4];
#pragma unroll
                    for (int mi = 0; mi < 2; mi++)
                        ldsm4(a[mi], st + (uint32_t)((m0w + mi * 16 + a_lrow) * 144 + (kl + a_lkoff) * 2));
#pragma unroll
                    for (int nh = 0; nh < 4; nh++) {
                        uint32_t t4[4];
                        ldsm4t(t4, st + 18432u +
                                   (uint32_t)((kl + b_lk) * 272 + (n0w + nh * 16 + b_ln) * 2));
#pragma unroll
                        for (int mi = 0; mi < 2; mi++) {
                            mma16816(acc[mi][nh * 2 + 0], a[mi], t4);
                            mma16816(acc[mi][nh * 2 + 1], a[mi], t4 + 2);
                        }
                    }
                }
            }

            // epilogue: weighted scatter-add
            const int g = lane >> 2, tq = lane & 3;
#pragma unroll
            for (int mi = 0; mi < 2; mi++)
#pragma unroll
                for (int rp = 0; rp < 2; rp++) {
                    const int rloc = m0w + mi * 16 + rp * 8 + g;
                    const int tok = rows[rloc];
                    const float wt = ws[rloc];
                    if (wt != 0.f) {
                        float* dst = out + (size_t)tok * H_DIM + n0 + n0w + tq * 2;
#pragma unroll
                        for (int ni = 0; ni < 8; ni++) {
                            atomicAdd(dst + ni * 8 + 0, wt * acc[mi][ni][rp * 2 + 0]);
                            atomicAdd(dst + ni * 8 + 1, wt * acc[mi][ni][rp * 2 + 1]);
                        }
                    }
                }
        }
    }

    // safety: finish any conversion chunks this CTA still owns
    while (conv_next < 4) { conv_chunk(blockIdx.x + conv_next * GEMM_GRID, w2f); conv_next++; }
}

// ---------------- launch ----------------------------------------------------
extern "C" void kernel_launch(void* const* d_in, const int* in_sizes, int n_in,
                              void* d_out, int out_size) {
    const float* x  = (const float*)d_in[0];
    const float* gw = (const float*)d_in[1];
    const float* w1 = (const float*)d_in[2];
    const float* w2 = (const float*)d_in[3];
    const float* w3 = (const float*)d_in[4];
    float* out = (float*)d_out;

    cudaFuncSetAttribute(moe_gemm_kernel, cudaFuncAttributeMaxDynamicSharedMemorySize, G_SMEM);

    prep_kernel<<<PREP_GRID, 256>>>(x, gw, w1, w3, (float4*)out);
    assign_kernel<<<1, 256>>>();
    moe_gemm_kernel<<<GEMM_GRID, 256, G_SMEM>>>(w2, out);
}